// round 14
// baseline (speedup 1.0000x reference)
#include <cuda_runtime.h>
#include <cuda_fp16.h>
#include <math.h>
#include <stdint.h>

#define HD   512
#define BD   32
#define SD   2048
#define K2   1024
#define W4H  2048
#define NEGV (-1e10f)

#define TPB  512
#define NCH  16            /* k chunks of 64 */

#define OFF_A32 0          /* 128 rows * 256B fp32 = 32KB */
#define OFF_A16 32768      /* 128 rows * 128B fp16 = 16KB */
#define OFF_B   49152      /* 256 rows * 128B fp16 = 32KB */
#define BUFSZ   81920
#define SMEM_TOTAL (2 * BUFSZ)

__device__ float g_hb[BD * HD];
__device__ float g_attnp[2 * BD * SD];
__device__ __align__(16) __half g_wh[HD * K2];

// ---------------------------------------------------------------- helpers
__device__ __forceinline__ uint32_t smem_u32(const void* p) {
    uint32_t a;
    asm("{ .reg .u64 t; cvta.to.shared.u64 t, %1; cvt.u32.u64 %0, t; }"
        : "=r"(a) : "l"(p));
    return a;
}
__device__ __forceinline__ void cp16(uint32_t dst, const void* src) {
    asm volatile("cp.async.cg.shared.global [%0], [%1], 16;"
                 :: "r"(dst), "l"(src) : "memory");
}
__device__ __forceinline__ void ldmx4(uint32_t* r, uint32_t addr) {
    asm volatile("ldmatrix.sync.aligned.m8n8.x4.shared.b16 {%0,%1,%2,%3}, [%4];"
                 : "=r"(r[0]), "=r"(r[1]), "=r"(r[2]), "=r"(r[3]) : "r"(addr));
}
__device__ __forceinline__ void hmma(float* c, const uint32_t* a,
                                     uint32_t b0, uint32_t b1) {
    asm("mma.sync.aligned.m16n8k16.row.col.f32.f16.f16.f32 "
        "{%0,%1,%2,%3}, {%4,%5,%6,%7}, {%8,%9}, {%0,%1,%2,%3};"
        : "+f"(c[0]), "+f"(c[1]), "+f"(c[2]), "+f"(c[3])
        : "r"(a[0]), "r"(a[1]), "r"(a[2]), "r"(a[3]), "r"(b0), "r"(b1));
}

// FMA-pipe-only tanh (no MUFU). |err| <= ~2.3e-5.
__device__ __forceinline__ float tanh_fast(float x) {
    float xa = fminf(fmaxf(x, -5.7f), 5.7f);
    float z  = xa * 2.885390081777927f;
    float fz = z + 12582912.0f;
    int   ni = __float_as_int(fz);
    float f  = z - (fz - 12582912.0f);
    float p  = 1.3333558146e-3f;
    p = fmaf(p, f, 9.6181291076e-3f);
    p = fmaf(p, f, 5.5504108664e-2f);
    p = fmaf(p, f, 2.4022650696e-1f);
    p = fmaf(p, f, 6.9314718056e-1f);
    p = fmaf(p, f, 1.0f);
    float s = __int_as_float((ni << 23) + 0x3F800000);
    float t = p * s;
    float d = t + 1.0f;
    float r = __int_as_float(0x7EF311C3 - __float_as_int(d));
    r = r * (2.0f - d * r);
    r = r * (2.0f - d * r);
    r = r * (2.0f - d * r);
    return (t - 1.0f) * r;
}

// ---------------- hb + prep_w (256 blocks, ~14.5us measured)
__global__ void hb_prepw_kernel(const float* __restrict__ hidden,
                                const float* __restrict__ attn_w,
                                const float* __restrict__ attn_b) {
    int bid = blockIdx.x;                // 0..255
    int hc = bid & 7, b = bid >> 3;

    {   // prep_w: 2 W rows per block -> 512 rows total
        #pragma unroll
        for (int rr = 0; rr < 2; rr++) {
            int n = bid * 2 + rr;
            int k = threadIdx.x * 4;
            float4 w = *(const float4*)(attn_w + (size_t)n * W4H + 1024 + k);
            __half2 h01 = __floats2half2_rn(w.x * 64.f, w.y * 64.f);
            __half2 h23 = __floats2half2_rn(w.z * 64.f, w.w * 64.f);
            *(uint2*)(g_wh + (size_t)n * K2 + k) =
                make_uint2(*(uint32_t*)&h01, *(uint32_t*)&h23);
        }
    }

    __shared__ float sh[K2];
    for (int i = threadIdx.x; i < K2; i += 256) sh[i] = hidden[b * K2 + i];
    __syncthreads();
    int w = threadIdx.x >> 5, lane = threadIdx.x & 31;
    #pragma unroll
    for (int hi = 0; hi < 8; hi++) {
        int h = hc * 64 + w * 8 + hi;
        const float* wr = attn_w + (size_t)h * W4H;
        float s = 0.f;
        for (int k = lane * 4; k < K2; k += 128) {
            float4 wv = *(const float4*)(wr + k);
            s += sh[k] * wv.x + sh[k + 1] * wv.y + sh[k + 2] * wv.z + sh[k + 3] * wv.w;
        }
        #pragma unroll
        for (int o = 16; o > 0; o >>= 1) s += __shfl_down_sync(0xffffffffu, s, o);
        if (lane == 0) g_hb[b * HD + h] = s + attn_b[h];
    }
}

// ---------------- energy: fp16 HMMA GEMM, A fp32 + pipelined in-loop convert
__global__ void __launch_bounds__(TPB, 1)
energy_kernel(const float* __restrict__ eo, const float* __restrict__ v) {
    extern __shared__ char smem[];
    const uint32_t sb = smem_u32(smem);
    const int tid  = threadIdx.x;
    const int lane = tid & 31;
    const int warp = tid >> 5;
    const int wm   = warp >> 2;          // 0..3  (m32 quarter)
    const int wn   = warp & 3;           // 0..3  (n64 quarter)

    const int m0  = blockIdx.x * 128;
    const int nsl = blockIdx.y;
    const int n0  = nsl * 256;

    float acc[2][8][4];
    #pragma unroll
    for (int mf = 0; mf < 2; mf++)
        #pragma unroll
        for (int nf = 0; nf < 8; nf++)
            #pragma unroll
            for (int i = 0; i < 4; i++) acc[mf][nf][i] = 0.f;

    const int a_rg = (lane & 7) + ((lane >> 3) & 1) * 8;
    const int a_u  = lane >> 4;
    const int b_rg = (lane & 7) + ((lane >> 4) << 3);
    const int b_u  = (lane >> 3) & 1;

    auto issue = [&](int kc, int buf) {
        const uint32_t bs = sb + buf * BUFSZ;
        #pragma unroll
        for (int j = 0; j < 4; j++) {       // A fp32: 128 rows x 16 units = 2048
            int x = tid + j * TPB;
            int r = x >> 4, u = x & 15;
            cp16(bs + OFF_A32 + (uint32_t)(r * 256 + u * 16),
                 eo + (size_t)(m0 + r) * K2 + kc + u * 4);
        }
        #pragma unroll
        for (int j = 0; j < 4; j++) {       // B fp16: 256 rows x 8 units = 2048
            int x = tid + j * TPB;
            int r = x >> 3, u = x & 7;
            uint32_t d = (uint32_t)(r * 128 + ((u ^ (r & 7)) << 4));
            cp16(bs + OFF_B + d, g_wh + (size_t)(n0 + r) * K2 + kc + u * 8);
        }
        asm volatile("cp.async.commit_group;" ::: "memory");
    };

    // one quarter of the A32 -> A16 (swizzled) convert
    auto convert_slice = [&](int j, int buf) {
        char* bp = smem + buf * BUFSZ;
        int idx = tid + j * TPB;            // 0..2047
        int r = idx >> 4, q = idx & 15;
        float4 x = *(const float4*)(bp + OFF_A32 + r * 256 + q * 16);
        __half2 h01 = __floats2half2_rn(x.x, x.y);
        __half2 h23 = __floats2half2_rn(x.z, x.w);
        int u = q >> 1;
        uint32_t d = (uint32_t)(r * 128 + ((u ^ (r & 7)) << 4) + (q & 1) * 8);
        *(uint2*)(bp + OFF_A16 + d) =
            make_uint2(*(uint32_t*)&h01, *(uint32_t*)&h23);
    };

    // prologue: chunk0 loaded + converted; chunk1 in flight
    issue(0, 0);
    asm volatile("cp.async.wait_group 0;" ::: "memory");
    __syncthreads();
    #pragma unroll
    for (int j = 0; j < 4; j++) convert_slice(j, 0);
    issue(64, 1);

    for (int c = 0; c < NCH; c++) {
        asm volatile("cp.async.wait_group 0;" ::: "memory");
        __syncthreads();   // convert(c) writes + chunk c+1 data visible

        const uint32_t bs = sb + (c & 1) * BUFSZ;
        const int nbuf = (c + 1) & 1;
        const bool cvt = (c + 1 < NCH);

        #pragma unroll
        for (int ks = 0; ks < 4; ks++) {
            if (cvt) convert_slice(ks, nbuf);   // hide in tensor shadow
            uint32_t af[2][4];
            #pragma unroll
            for (int mf = 0; mf < 2; mf++) {
                int row = wm * 32 + mf * 16 + a_rg;
                int u   = ks * 2 + a_u;
                ldmx4(af[mf], bs + OFF_A16 + (uint32_t)(row * 128 + ((u ^ (row & 7)) << 4)));
            }
            #pragma unroll
            for (int g = 0; g < 4; g++) {
                uint32_t bf[4];
                int row = wn * 64 + g * 16 + b_rg;
                int u   = ks * 2 + b_u;
                ldmx4(bf, bs + OFF_B + (uint32_t)(row * 128 + ((u ^ (row & 7)) << 4)));
                #pragma unroll
                for (int mf = 0; mf < 2; mf++) {
                    hmma(acc[mf][g * 2],     af[mf], bf[0], bf[1]);
                    hmma(acc[mf][g * 2 + 1], af[mf], bf[2], bf[3]);
                }
            }
        }
        __syncthreads();   // compute(c) done before buffers (c&1) are overwritten
        if (c + 2 < NCH) issue((c + 2) * 64, c & 1);
    }

    // -------- epilogue: tanh(E/64 + hb) . v
    float* hb_t = (float*)smem;                    // [256][33]
    float* v_s  = (float*)(smem + 33792);          // [256]
    float* red  = (float*)(smem + 34816);          // [128][4]
    for (int i = tid; i < 256 * BD; i += TPB) {
        int n = i >> 5, b = i & 31;
        hb_t[n * 33 + b] = g_hb[b * HD + n0 + n];
    }
    if (tid < 256) v_s[tid] = v[n0 + tid];
    __syncthreads();

    const float c1 = 1.0f / 64.0f;
    const int quad = lane >> 2, qlane = lane & 3;
    #pragma unroll
    for (int mf = 0; mf < 2; mf++) {
        #pragma unroll
        for (int h = 0; h < 2; h++) {
            int rl = wm * 32 + mf * 16 + h * 8 + quad;
            int b  = (m0 + rl) & 31;
            float p = 0.f;
            #pragma unroll
            for (int nf = 0; nf < 8; nf++) {
                int cl = wn * 64 + nf * 8 + qlane * 2;
                float e0 = fmaf(acc[mf][nf][h * 2],     c1, hb_t[cl * 33 + b]);
                float e1 = fmaf(acc[mf][nf][h * 2 + 1], c1, hb_t[(cl + 1) * 33 + b]);
                p = fmaf(tanh_fast(e0), v_s[cl],     p);
                p = fmaf(tanh_fast(e1), v_s[cl + 1], p);
            }
            p += __shfl_xor_sync(0xffffffffu, p, 1);
            p += __shfl_xor_sync(0xffffffffu, p, 2);
            if (qlane == 0) red[rl * 4 + wn] = p;
        }
    }
    __syncthreads();
    if (tid < 128) {
        int m = m0 + tid;
        float lg = red[tid * 4] + red[tid * 4 + 1] + red[tid * 4 + 2] + red[tid * 4 + 3];
        g_attnp[nsl * BD * SD + (m & 31) * SD + (m >> 5)] = lg;
    }
}

// ---------------- softmax over S per batch row (sums 2 N-slice partials)
__global__ void softmax_kernel(const int* __restrict__ mask, float* __restrict__ out) {
    int b = blockIdx.x;
    int tid = threadIdx.x;             // 256
    int warp = tid >> 5, lane = tid & 31;
    __shared__ float sred[8];

    float vals[8];
    float mx = -INFINITY;
    #pragma unroll
    for (int i = 0; i < 8; i++) {
        int s = tid + i * 256;
        float raw = g_attnp[b * SD + s] + g_attnp[BD * SD + b * SD + s];
        vals[i] = mask[b * SD + s] ? raw : NEGV;
        mx = fmaxf(mx, vals[i]);
    }
    #pragma unroll
    for (int o = 16; o > 0; o >>= 1) mx = fmaxf(mx, __shfl_xor_sync(0xffffffffu, mx, o));
    if (lane == 0) sred[warp] = mx;
    __syncthreads();
    float bm = sred[0];
    #pragma unroll
    for (int w = 1; w < 8; w++) bm = fmaxf(bm, sred[w]);

    float sum = 0.f;
    #pragma unroll
    for (int i = 0; i < 8; i++) {
        vals[i] = expf(vals[i] - bm);
        sum += vals[i];
    }
    #pragma unroll
    for (int o = 16; o > 0; o >>= 1) sum += __shfl_xor_sync(0xffffffffu, sum, o);
    __syncthreads();
    if (lane == 0) sred[warp] = sum;
    __syncthreads();
    float bs = 0.f;
    #pragma unroll
    for (int w = 0; w < 8; w++) bs += sred[w];
    float inv = 1.f / bs;
    #pragma unroll
    for (int i = 0; i < 8; i++) out[b * SD + tid + i * 256] = vals[i] * inv;
}

extern "C" void kernel_launch(void* const* d_in, const int* in_sizes, int n_in,
                              void* d_out, int out_size) {
    const float* hidden = (const float*)d_in[0];
    const float* eo     = (const float*)d_in[1];
    const int*   mask   = (const int*)  d_in[2];
    const float* attn_w = (const float*)d_in[3];
    const float* attn_b = (const float*)d_in[4];
    const float* v      = (const float*)d_in[5];
    float* out = (float*)d_out;

    cudaFuncSetAttribute(energy_kernel,
                         cudaFuncAttributeMaxDynamicSharedMemorySize, SMEM_TOTAL);

    hb_prepw_kernel<<<256, 256>>>(hidden, attn_w, attn_b);
    energy_kernel<<<dim3(SD * BD / 128, 2), TPB, SMEM_TOTAL>>>(eo, v);
    softmax_kernel<<<BD, 256>>>(mask, out);
}

// round 15
// speedup vs baseline: 1.2473x; 1.2473x over previous
#include <cuda_runtime.h>
#include <cuda_fp16.h>
#include <math.h>
#include <stdint.h>

#define HD   512
#define BD   32
#define SD   2048
#define K2   1024
#define W4H  2048
#define NEGV (-1e10f)

#define TPB  512
#define NCH  16            /* k chunks of 64 */

/* smem: A32 x3 (32KB), A16 x2 (16KB), B x3 (32KB) = 224KB */
#define A32_OFF(s) ((s) * 32768)
#define A16_OFF(p) (98304 + (p) * 16384)
#define B_OFF(s)   (131072 + (s) * 32768)
#define SMEM_TOTAL 229376

__device__ float g_hb[BD * HD];
__device__ float g_attnp[2 * BD * SD];
__device__ __align__(16) __half g_wh[HD * K2];

// ---------------------------------------------------------------- helpers
__device__ __forceinline__ uint32_t smem_u32(const void* p) {
    uint32_t a;
    asm("{ .reg .u64 t; cvta.to.shared.u64 t, %1; cvt.u32.u64 %0, t; }"
        : "=r"(a) : "l"(p));
    return a;
}
__device__ __forceinline__ void cp16(uint32_t dst, const void* src) {
    asm volatile("cp.async.cg.shared.global [%0], [%1], 16;"
                 :: "r"(dst), "l"(src) : "memory");
}
__device__ __forceinline__ void ldmx4(uint32_t* r, uint32_t addr) {
    asm volatile("ldmatrix.sync.aligned.m8n8.x4.shared.b16 {%0,%1,%2,%3}, [%4];"
                 : "=r"(r[0]), "=r"(r[1]), "=r"(r[2]), "=r"(r[3]) : "r"(addr));
}
__device__ __forceinline__ void hmma(float* c, const uint32_t* a,
                                     uint32_t b0, uint32_t b1) {
    asm("mma.sync.aligned.m16n8k16.row.col.f32.f16.f16.f32 "
        "{%0,%1,%2,%3}, {%4,%5,%6,%7}, {%8,%9}, {%0,%1,%2,%3};"
        : "+f"(c[0]), "+f"(c[1]), "+f"(c[2]), "+f"(c[3])
        : "r"(a[0]), "r"(a[1]), "r"(a[2]), "r"(a[3]), "r"(b0), "r"(b1));
}

// FMA-pipe-only tanh (no MUFU). |err| <= ~2.3e-5.
__device__ __forceinline__ float tanh_fast(float x) {
    float xa = fminf(fmaxf(x, -5.7f), 5.7f);
    float z  = xa * 2.885390081777927f;
    float fz = z + 12582912.0f;
    int   ni = __float_as_int(fz);
    float f  = z - (fz - 12582912.0f);
    float p  = 1.3333558146e-3f;
    p = fmaf(p, f, 9.6181291076e-3f);
    p = fmaf(p, f, 5.5504108664e-2f);
    p = fmaf(p, f, 2.4022650696e-1f);
    p = fmaf(p, f, 6.9314718056e-1f);
    p = fmaf(p, f, 1.0f);
    float s = __int_as_float((ni << 23) + 0x3F800000);
    float t = p * s;
    float d = t + 1.0f;
    float r = __int_as_float(0x7EF311C3 - __float_as_int(d));
    r = r * (2.0f - d * r);
    r = r * (2.0f - d * r);
    r = r * (2.0f - d * r);
    return (t - 1.0f) * r;
}

// ---------------- hb + prep_w (256 blocks, ~14us measured)
__global__ void hb_prepw_kernel(const float* __restrict__ hidden,
                                const float* __restrict__ attn_w,
                                const float* __restrict__ attn_b) {
    int bid = blockIdx.x;                // 0..255
    int hc = bid & 7, b = bid >> 3;

    {   // prep_w: 2 W rows per block -> 512 rows total
        #pragma unroll
        for (int rr = 0; rr < 2; rr++) {
            int n = bid * 2 + rr;
            int k = threadIdx.x * 4;
            float4 w = *(const float4*)(attn_w + (size_t)n * W4H + 1024 + k);
            __half2 h01 = __floats2half2_rn(w.x * 64.f, w.y * 64.f);
            __half2 h23 = __floats2half2_rn(w.z * 64.f, w.w * 64.f);
            *(uint2*)(g_wh + (size_t)n * K2 + k) =
                make_uint2(*(uint32_t*)&h01, *(uint32_t*)&h23);
        }
    }

    __shared__ float sh[K2];
    for (int i = threadIdx.x; i < K2; i += 256) sh[i] = hidden[b * K2 + i];
    __syncthreads();
    int w = threadIdx.x >> 5, lane = threadIdx.x & 31;
    #pragma unroll
    for (int hi = 0; hi < 8; hi++) {
        int h = hc * 64 + w * 8 + hi;
        const float* wr = attn_w + (size_t)h * W4H;
        float s = 0.f;
        for (int k = lane * 4; k < K2; k += 128) {
            float4 wv = *(const float4*)(wr + k);
            s += sh[k] * wv.x + sh[k + 1] * wv.y + sh[k + 2] * wv.z + sh[k + 3] * wv.w;
        }
        #pragma unroll
        for (int o = 16; o > 0; o >>= 1) s += __shfl_down_sync(0xffffffffu, s, o);
        if (lane == 0) g_hb[b * HD + h] = s + attn_b[h];
    }
}

// ---------------- energy: fp16 HMMA, triple-buffered A32/B, shadow convert
__global__ void __launch_bounds__(TPB, 1)
energy_kernel(const float* __restrict__ eo, const float* __restrict__ v) {
    extern __shared__ char smem[];
    const uint32_t sb = smem_u32(smem);
    const int tid  = threadIdx.x;
    const int lane = tid & 31;
    const int warp = tid >> 5;
    const int wm   = warp >> 2;          // 0..3  (m32 quarter)
    const int wn   = warp & 3;           // 0..3  (n64 quarter)

    const int m0  = blockIdx.x * 128;
    const int nsl = blockIdx.y;
    const int n0  = nsl * 256;

    float acc[2][8][4];
    #pragma unroll
    for (int mf = 0; mf < 2; mf++)
        #pragma unroll
        for (int nf = 0; nf < 8; nf++)
            #pragma unroll
            for (int i = 0; i < 4; i++) acc[mf][nf][i] = 0.f;

    const int a_rg = (lane & 7) + ((lane >> 3) & 1) * 8;
    const int a_u  = lane >> 4;
    const int b_rg = (lane & 7) + ((lane >> 4) << 3);
    const int b_u  = (lane >> 3) & 1;

    auto issue = [&](int chunk) {
        const int kc = chunk * 64;
        const int s  = chunk % 3;
        const uint32_t a32 = sb + A32_OFF(s);
        const uint32_t bb  = sb + B_OFF(s);
        #pragma unroll
        for (int j = 0; j < 4; j++) {       // A fp32: 128 rows x 16 units = 2048
            int x = tid + j * TPB;
            int r = x >> 4, u = x & 15;
            cp16(a32 + (uint32_t)(r * 256 + u * 16),
                 eo + (size_t)(m0 + r) * K2 + kc + u * 4);
        }
        #pragma unroll
        for (int j = 0; j < 4; j++) {       // B fp16: 256 rows x 8 units = 2048
            int x = tid + j * TPB;
            int r = x >> 3, u = x & 7;
            uint32_t d = (uint32_t)(r * 128 + ((u ^ (r & 7)) << 4));
            cp16(bb + d, g_wh + (size_t)(n0 + r) * K2 + kc + u * 8);
        }
        asm volatile("cp.async.commit_group;" ::: "memory");
    };

    // one quarter of A32(chunk) -> A16(chunk&1), swizzled
    auto convert_slice = [&](int j, int chunk) {
        char* src = smem + A32_OFF(chunk % 3);
        char* dst = smem + A16_OFF(chunk & 1);
        int idx = tid + j * TPB;            // 0..2047
        int r = idx >> 4, q = idx & 15;
        float4 x = *(const float4*)(src + r * 256 + q * 16);
        __half2 h01 = __floats2half2_rn(x.x, x.y);
        __half2 h23 = __floats2half2_rn(x.z, x.w);
        int u = q >> 1;
        uint32_t d = (uint32_t)(r * 128 + ((u ^ (r & 7)) << 4) + (q & 1) * 8);
        *(uint2*)(dst + d) = make_uint2(*(uint32_t*)&h01, *(uint32_t*)&h23);
    };

    // prologue: chunk0 arrived+converted; chunks 1,2 in flight
    issue(0);
    issue(1);
    asm volatile("cp.async.wait_group 1;" ::: "memory");   // chunk0 arrived
    __syncthreads();
    #pragma unroll
    for (int j = 0; j < 4; j++) convert_slice(j, 0);
    issue(2);

    for (int c = 0; c < NCH; c++) {
        // guarantee chunk c+1 arrived; keep chunk c+2 copy in flight
        if (c + 2 < NCH) asm volatile("cp.async.wait_group 1;" ::: "memory");
        else             asm volatile("cp.async.wait_group 0;" ::: "memory");
        __syncthreads();   // + convert(c) writes visible

        const uint32_t a16 = sb + A16_OFF(c & 1);
        const uint32_t bb  = sb + B_OFF(c % 3);
        const bool cvt = (c + 1 < NCH);

        #pragma unroll
        for (int ks = 0; ks < 4; ks++) {
            if (cvt) convert_slice(ks, c + 1);   // hidden in tensor shadow
            uint32_t af[2][4];
            #pragma unroll
            for (int mf = 0; mf < 2; mf++) {
                int row = wm * 32 + mf * 16 + a_rg;
                int u   = ks * 2 + a_u;
                ldmx4(af[mf], a16 + (uint32_t)(row * 128 + ((u ^ (row & 7)) << 4)));
            }
            #pragma unroll
            for (int g = 0; g < 4; g++) {
                uint32_t bf[4];
                int row = wn * 64 + g * 16 + b_rg;
                int u   = ks * 2 + b_u;
                ldmx4(bf, bb + (uint32_t)(row * 128 + ((u ^ (row & 7)) << 4)));
                #pragma unroll
                for (int mf = 0; mf < 2; mf++) {
                    hmma(acc[mf][g * 2],     af[mf], bf[0], bf[1]);
                    hmma(acc[mf][g * 2 + 1], af[mf], bf[2], bf[3]);
                }
            }
        }
        __syncthreads();   // compute(c)+convert(c+1) done before slot reuse
        if (c + 3 < NCH) issue(c + 3);
    }

    // -------- epilogue: tanh(E/64 + hb) . v
    float* hb_t = (float*)smem;                    // [256][33]
    float* v_s  = (float*)(smem + 33792);          // [256]
    float* red  = (float*)(smem + 34816);          // [128][4]
    for (int i = tid; i < 256 * BD; i += TPB) {
        int n = i >> 5, b = i & 31;
        hb_t[n * 33 + b] = g_hb[b * HD + n0 + n];
    }
    if (tid < 256) v_s[tid] = v[n0 + tid];
    __syncthreads();

    const float c1 = 1.0f / 64.0f;
    const int quad = lane >> 2, qlane = lane & 3;
    #pragma unroll
    for (int mf = 0; mf < 2; mf++) {
        #pragma unroll
        for (int h = 0; h < 2; h++) {
            int rl = wm * 32 + mf * 16 + h * 8 + quad;
            int b  = (m0 + rl) & 31;
            float p = 0.f;
            #pragma unroll
            for (int nf = 0; nf < 8; nf++) {
                int cl = wn * 64 + nf * 8 + qlane * 2;
                float e0 = fmaf(acc[mf][nf][h * 2],     c1, hb_t[cl * 33 + b]);
                float e1 = fmaf(acc[mf][nf][h * 2 + 1], c1, hb_t[(cl + 1) * 33 + b]);
                p = fmaf(tanh_fast(e0), v_s[cl],     p);
                p = fmaf(tanh_fast(e1), v_s[cl + 1], p);
            }
            p += __shfl_xor_sync(0xffffffffu, p, 1);
            p += __shfl_xor_sync(0xffffffffu, p, 2);
            if (qlane == 0) red[rl * 4 + wn] = p;
        }
    }
    __syncthreads();
    if (tid < 128) {
        int m = m0 + tid;
        float lg = red[tid * 4] + red[tid * 4 + 1] + red[tid * 4 + 2] + red[tid * 4 + 3];
        g_attnp[nsl * BD * SD + (m & 31) * SD + (m >> 5)] = lg;
    }
}

// ---------------- softmax over S per batch row (sums 2 N-slice partials)
__global__ void softmax_kernel(const int* __restrict__ mask, float* __restrict__ out) {
    int b = blockIdx.x;
    int tid = threadIdx.x;             // 256
    int warp = tid >> 5, lane = tid & 31;
    __shared__ float sred[8];

    float vals[8];
    float mx = -INFINITY;
    #pragma unroll
    for (int i = 0; i < 8; i++) {
        int s = tid + i * 256;
        float raw = g_attnp[b * SD + s] + g_attnp[BD * SD + b * SD + s];
        vals[i] = mask[b * SD + s] ? raw : NEGV;
        mx = fmaxf(mx, vals[i]);
    }
    #pragma unroll
    for (int o = 16; o > 0; o >>= 1) mx = fmaxf(mx, __shfl_xor_sync(0xffffffffu, mx, o));
    if (lane == 0) sred[warp] = mx;
    __syncthreads();
    float bm = sred[0];
    #pragma unroll
    for (int w = 1; w < 8; w++) bm = fmaxf(bm, sred[w]);

    float sum = 0.f;
    #pragma unroll
    for (int i = 0; i < 8; i++) {
        vals[i] = expf(vals[i] - bm);
        sum += vals[i];
    }
    #pragma unroll
    for (int o = 16; o > 0; o >>= 1) sum += __shfl_xor_sync(0xffffffffu, sum, o);
    __syncthreads();
    if (lane == 0) sred[warp] = sum;
    __syncthreads();
    float bs = 0.f;
    #pragma unroll
    for (int w = 0; w < 8; w++) bs += sred[w];
    float inv = 1.f / bs;
    #pragma unroll
    for (int i = 0; i < 8; i++) out[b * SD + tid + i * 256] = vals[i] * inv;
}

extern "C" void kernel_launch(void* const* d_in, const int* in_sizes, int n_in,
                              void* d_out, int out_size) {
    const float* hidden = (const float*)d_in[0];
    const float* eo     = (const float*)d_in[1];
    const int*   mask   = (const int*)  d_in[2];
    const float* attn_w = (const float*)d_in[3];
    const float* attn_b = (const float*)d_in[4];
    const float* v      = (const float*)d_in[5];
    float* out = (float*)d_out;

    cudaFuncSetAttribute(energy_kernel,
                         cudaFuncAttributeMaxDynamicSharedMemorySize, SMEM_TOTAL);

    hb_prepw_kernel<<<256, 256>>>(hidden, attn_w, attn_b);
    energy_kernel<<<dim3(SD * BD / 128, 2), TPB, SMEM_TOTAL>>>(eo, v);
    softmax_kernel<<<BD, 256>>>(mask, out);
}